// round 15
// baseline (speedup 1.0000x reference)
#include <cuda_runtime.h>
#include <cuda_bf16.h>
#include <math.h>
#include <stdint.h>

// Problem constants
constexpr int BB   = 2;
constexpr int LL   = 1024;
constexpr int DD   = 768;
constexpr int NLAY = 8;
constexpr int DIN  = 1536;       // 2*D
constexpr int NSS  = 16;
constexpr int DRR  = 48;         // D/16
constexpr int KCC  = 4;
constexpr int TT   = BB * LL;    // 2048 tokens
constexpr int NR   = DRR + 2 * NSS;  // 80 (logical)
constexpr int NRP  = 128;        // padded x_proj partial row stride

// Chunked scan
constexpr int CH = 16;
constexpr int CS = LL / CH;      // 64
constexpr int NSTATE = BB * DIN * NSS;   // 49152

// split-K factors
constexpr int XK = 8;            // x_proj
constexpr int XKS = DIN / XK;    // 192
constexpr int OK = 3;            // out_proj
constexpr int OKS = DIN / OK;    // 512
constexpr int DTK = 64;          // dt padded K

// fp32 scratch
constexpr size_t O_RES = 0;
constexpr size_t O_XZ  = O_RES + (size_t)TT * DD;
constexpr size_t O_XC  = O_XZ  + (size_t)TT * 2 * DIN;
constexpr size_t O_DT  = O_XC  + (size_t)TT * DIN;   // dtT [DIN][TT]
constexpr size_t O_END = O_DT  + (size_t)DIN * TT;
__device__ float g_buf[O_END];

__device__ float g_hend[(size_t)CH * NSTATE];
__device__ float g_P[(size_t)CH * NSTATE];
__device__ float g_xf_part[OK][(size_t)TT * DD];
__device__ float g_xp_part[XK][(size_t)TT * NRP];
__device__ float g_dbcBC[(size_t)TT * 32];       // [t][0..15]=B, [16..31]=C

// bf16 hi/lo activation + weight buffers
constexpr size_t NWI  = (size_t)NLAY * 2 * DIN * DD;
constexpr size_t NWO  = (size_t)NLAY * DD * DIN;
constexpr size_t NWX  = (size_t)NLAY * NRP * DIN;
constexpr size_t NWDT = (size_t)NLAY * DIN * DTK;
__device__ __nv_bfloat16 g_xn_h[(size_t)TT * DD];
__device__ __nv_bfloat16 g_xn_l[(size_t)TT * DD];
__device__ __nv_bfloat16 g_y_h[(size_t)TT * DIN];
__device__ __nv_bfloat16 g_y_l[(size_t)TT * DIN];
__device__ __nv_bfloat16 g_xc_h[(size_t)TT * DIN];
__device__ __nv_bfloat16 g_xc_l[(size_t)TT * DIN];
__device__ __nv_bfloat16 g_dtA_h[(size_t)TT * DTK];
__device__ __nv_bfloat16 g_dtA_l[(size_t)TT * DTK];
__device__ __nv_bfloat16 g_wi_h[NWI];
__device__ __nv_bfloat16 g_wi_l[NWI];
__device__ __nv_bfloat16 g_wo_h[NWO];
__device__ __nv_bfloat16 g_wo_l[NWO];
__device__ __nv_bfloat16 g_wx_h[NWX];
__device__ __nv_bfloat16 g_wx_l[NWX];
__device__ __nv_bfloat16 g_wdt_h[NWDT];
__device__ __nv_bfloat16 g_wdt_l[NWDT];

// ---------------------------------------------------------------------------
// helpers
// ---------------------------------------------------------------------------
__device__ __forceinline__ void split_store(float v, __nv_bfloat16* H,
                                            __nv_bfloat16* L, size_t i) {
    __nv_bfloat16 h = __float2bfloat16(v);
    H[i] = h;
    L[i] = __float2bfloat16(v - __bfloat162float(h));
}

// packed 4-wide split store (i must be 2-aligned)
__device__ __forceinline__ void split_store4(float4 v, __nv_bfloat16* H,
                                             __nv_bfloat16* L, size_t i) {
    __nv_bfloat162 h0 = __floats2bfloat162_rn(v.x, v.y);
    __nv_bfloat162 h1 = __floats2bfloat162_rn(v.z, v.w);
    __nv_bfloat162 l0 = __floats2bfloat162_rn(v.x - __low2float(h0),
                                              v.y - __high2float(h0));
    __nv_bfloat162 l1 = __floats2bfloat162_rn(v.z - __low2float(h1),
                                              v.w - __high2float(h1));
    *reinterpret_cast<__nv_bfloat162*>(H + i)     = h0;
    *reinterpret_cast<__nv_bfloat162*>(H + i + 2) = h1;
    *reinterpret_cast<__nv_bfloat162*>(L + i)     = l0;
    *reinterpret_cast<__nv_bfloat162*>(L + i + 2) = l1;
}

__device__ __forceinline__ void split_store2(float a, float b, __nv_bfloat16* H,
                                             __nv_bfloat16* L, size_t i) {
    __nv_bfloat162 h = __floats2bfloat162_rn(a, b);
    __nv_bfloat162 l = __floats2bfloat162_rn(a - __low2float(h),
                                             b - __high2float(h));
    *reinterpret_cast<__nv_bfloat162*>(H + i) = h;
    *reinterpret_cast<__nv_bfloat162*>(L + i) = l;
}

__global__ void cvt_weights_kernel(const float* __restrict__ wi,
                                   const float* __restrict__ wo,
                                   const float* __restrict__ wx,
                                   const float* __restrict__ wdt) {
    size_t i = (size_t)blockIdx.x * 256 + threadIdx.x;
    if (i < NWI) { split_store(wi[i], g_wi_h, g_wi_l, i); return; }
    i -= NWI;
    if (i < NWO) { split_store(wo[i], g_wo_h, g_wo_l, i); return; }
    i -= NWO;
    if (i < NWX) {
        size_t k = i % DIN;
        size_t r = (i / DIN) % NRP;
        size_t l = i / ((size_t)DIN * NRP);
        float v = (r < NR) ? wx[(l * NR + r) * DIN + k] : 0.f;
        split_store(v, g_wx_h, g_wx_l, i);
        return;
    }
    i -= NWX;
    if (i < NWDT) {
        size_t k = i % DTK;
        size_t d = (i / DTK) % DIN;
        size_t l = i / ((size_t)DTK * DIN);
        float v = (k < DRR) ? wdt[(l * DIN + d) * DRR + k] : 0.f;
        split_store(v, g_wdt_h, g_wdt_l, i);
    }
}

// block reduction for 192 threads / 6 warps
__device__ __forceinline__ float block_sum_192(float v, float* red,
                                               int lane, int wid) {
#pragma unroll
    for (int o = 16; o > 0; o >>= 1)
        v += __shfl_xor_sync(0xffffffffu, v, o);
    if (lane == 0) red[wid] = v;
    __syncthreads();
    return red[0] + red[1] + red[2] + red[3] + red[4] + red[5];
}

// ---------------------------------------------------------------------------
// LayerNorm kernels: 192 threads, thread t owns elems 4t..4t+3 (float4).
// SRC 0: v = x (ln_first; res = v)
// SRC 1: v = sum of 3 out_proj partials (ln_fuse; res += v)
// SRC 2: v = sum of 3 partials + res (final; writes fp32 out, no bf16)
// ---------------------------------------------------------------------------
template <int SRC>
__global__ void __launch_bounds__(192)
ln_kernel(const float* __restrict__ x, float* __restrict__ res,
          __nv_bfloat16* __restrict__ xnh, __nv_bfloat16* __restrict__ xnl,
          const float* __restrict__ w, const float* __restrict__ b,
          float* __restrict__ out) {
    int row = blockIdx.x;
    size_t ro = (size_t)row * DD;
    int tid = threadIdx.x;
    int lane = tid & 31, wid = tid >> 5;
    int e = tid * 4;
    __shared__ float red[6];

    float4 v;
    if (SRC == 0) {
        v = *(const float4*)(x + ro + e);
    } else {
        float4 p0 = *(const float4*)(&g_xf_part[0][ro + e]);
        float4 p1 = *(const float4*)(&g_xf_part[1][ro + e]);
        float4 p2 = *(const float4*)(&g_xf_part[2][ro + e]);
        v = make_float4(p0.x + p1.x + p2.x, p0.y + p1.y + p2.y,
                        p0.z + p1.z + p2.z, p0.w + p1.w + p2.w);
        if (SRC == 2) {
            float4 r = *(const float4*)(res + ro + e);
            v.x += r.x; v.y += r.y; v.z += r.z; v.w += r.w;
        }
    }
    float mu = block_sum_192(v.x + v.y + v.z + v.w, red, lane, wid)
               * (1.f / DD);
    __syncthreads();
    float4 d = make_float4(v.x - mu, v.y - mu, v.z - mu, v.w - mu);
    float var = block_sum_192(d.x * d.x + d.y * d.y + d.z * d.z + d.w * d.w,
                              red, lane, wid) * (1.f / DD);
    float inv = rsqrtf(var + 1e-5f);
    float4 wv = *(const float4*)(w + e);
    float4 bv = *(const float4*)(b + e);
    float4 o = make_float4(d.x * inv * wv.x + bv.x, d.y * inv * wv.y + bv.y,
                           d.z * inv * wv.z + bv.z, d.w * inv * wv.w + bv.w);
    if (SRC == 2) {
        *(float4*)(out + ro + e) = o;
        return;
    }
    split_store4(o, xnh, xnl, ro + e);
    if (SRC == 0) {
        *(float4*)(res + ro + e) = v;
    } else {
        float4 r = *(const float4*)(res + ro + e);
        r.x += v.x; r.y += v.y; r.z += v.z; r.w += v.w;
        *(float4*)(res + ro + e) = r;
    }
}

// ===========================================================================
// Tensor-core GEMM (bf16 hi/lo, 3-pass), optional split-K + epilogue.
// EPI 0: plain.  EPI 2: bias[row] + softplus (transposed dt GEMM).
// ===========================================================================
__device__ __forceinline__ unsigned smem_u32(const void* p) {
    return (unsigned)__cvta_generic_to_shared(p);
}
__device__ __forceinline__ unsigned swz(int r, int c) {
    return (unsigned)(r * 64) + ((((unsigned)c >> 3) ^ (((unsigned)r >> 1) & 3u)) << 4);
}
__device__ __forceinline__ void ldsm_x4(unsigned* r, unsigned addr) {
    asm volatile("ldmatrix.sync.aligned.m8n8.x4.shared.b16 {%0,%1,%2,%3}, [%4];"
                 : "=r"(r[0]), "=r"(r[1]), "=r"(r[2]), "=r"(r[3]) : "r"(addr));
}
__device__ __forceinline__ void mma_bf16(float* c, const unsigned* a, const unsigned* b) {
    asm volatile(
        "mma.sync.aligned.m16n8k16.row.col.f32.bf16.bf16.f32 "
        "{%0,%1,%2,%3}, {%4,%5,%6,%7}, {%8,%9}, {%0,%1,%2,%3};"
        : "+f"(c[0]), "+f"(c[1]), "+f"(c[2]), "+f"(c[3])
        : "r"(a[0]), "r"(a[1]), "r"(a[2]), "r"(a[3]), "r"(b[0]), "r"(b[1]));
}
__device__ __forceinline__ void cp16(unsigned dst, const void* src) {
    asm volatile("cp.async.cg.shared.global [%0], [%1], 16;" :: "r"(dst), "l"(src));
}
__device__ __forceinline__ float softplus_f(float v) {
    return (v > 20.f) ? v : log1pf(__expf(v));
}

constexpr int STAGE_BYTES = 32768;
constexpr int NSTAGE = 3;
constexpr int ARR_A_H = 0, ARR_A_L = 8192, ARR_W_H = 16384, ARR_W_L = 24576;

template <int EPI>
__global__ void __launch_bounds__(256)
gemm_tc2_kernel(const __nv_bfloat16* __restrict__ Ahg,
                const __nv_bfloat16* __restrict__ Alg,
                const __nv_bfloat16* __restrict__ Whg,
                const __nv_bfloat16* __restrict__ Wlg,
                const float* __restrict__ bias,
                float* __restrict__ C, int ldc,
                int Ksplit, int Kfull, size_t partStride) {
    extern __shared__ __align__(16) unsigned char smraw[];
    const unsigned sbase = smem_u32(smraw);

    const int tid  = threadIdx.x;
    const int lane = tid & 31;
    const int warp = tid >> 5;
    const int wm = (warp & 1) * 64;
    const int wn = (warp >> 1) * 32;
    const int m0 = blockIdx.y * 128;
    const int n0 = blockIdx.x * 128;
    const int koff = blockIdx.z * Ksplit;
    float* Cout = C + (size_t)blockIdx.z * partStride;

    const int lrow = tid >> 1;
    const int lq0  = (tid & 1) * 2;
    const size_t aoff = (size_t)(m0 + lrow) * Kfull + koff;
    const size_t woff = (size_t)(n0 + lrow) * Kfull + koff;
    const unsigned sdst0 = (unsigned)(lrow * 64) +
                           (((unsigned)lq0 ^ (((unsigned)lrow >> 1) & 3u)) << 4);
    const unsigned sdst1 = (unsigned)(lrow * 64) +
                           ((((unsigned)lq0 + 1u) ^ (((unsigned)lrow >> 1) & 3u)) << 4);

    const int nsteps = Ksplit / 32;

    auto load_stage = [&](int buf, int k0) {
        unsigned sb = sbase + buf * STAGE_BYTES;
        const __nv_bfloat16* pa_h = Ahg + aoff + k0 + lq0 * 8;
        const __nv_bfloat16* pa_l = Alg + aoff + k0 + lq0 * 8;
        const __nv_bfloat16* pw_h = Whg + woff + k0 + lq0 * 8;
        const __nv_bfloat16* pw_l = Wlg + woff + k0 + lq0 * 8;
        cp16(sb + ARR_A_H + sdst0, pa_h);
        cp16(sb + ARR_A_H + sdst1, pa_h + 8);
        cp16(sb + ARR_A_L + sdst0, pa_l);
        cp16(sb + ARR_A_L + sdst1, pa_l + 8);
        cp16(sb + ARR_W_H + sdst0, pw_h);
        cp16(sb + ARR_W_H + sdst1, pw_h + 8);
        cp16(sb + ARR_W_L + sdst0, pw_l);
        cp16(sb + ARR_W_L + sdst1, pw_l + 8);
    };

    float acc[4][4][4];
#pragma unroll
    for (int i = 0; i < 4; i++)
#pragma unroll
        for (int j = 0; j < 4; j++)
#pragma unroll
            for (int q = 0; q < 4; q++) acc[i][j][q] = 0.f;

    load_stage(0, 0);
    asm volatile("cp.async.commit_group;");
    if (nsteps > 1) load_stage(1, 32);
    asm volatile("cp.async.commit_group;");

    const int arow = wm + (lane & 7) + (lane & 8);
    const int brow = wn + (lane & 7) + ((lane >> 4) << 3);

    for (int s = 0; s < nsteps; s++) {
        asm volatile("cp.async.wait_group 1;");
        __syncthreads();
        if (s + 2 < nsteps) load_stage((s + 2) % NSTAGE, (s + 2) * 32);
        asm volatile("cp.async.commit_group;");

        const unsigned sb = sbase + (s % NSTAGE) * STAGE_BYTES;
#pragma unroll
        for (int kk = 0; kk < 32; kk += 16) {
            const int acol = kk + ((lane >> 4) << 3);
            const int bcol = kk + (lane & 8);
            unsigned af[4][4];
            unsigned whf[4][2], wlf[4][2];
#pragma unroll
            for (int mi = 0; mi < 4; mi++)
                ldsm_x4(af[mi], sb + ARR_A_H + swz(arow + mi * 16, acol));
#pragma unroll
            for (int nj = 0; nj < 2; nj++) {
                unsigned r[4];
                ldsm_x4(r, sb + ARR_W_H + swz(brow + nj * 16, bcol));
                whf[nj * 2][0] = r[0]; whf[nj * 2][1] = r[1];
                whf[nj * 2 + 1][0] = r[2]; whf[nj * 2 + 1][1] = r[3];
                ldsm_x4(r, sb + ARR_W_L + swz(brow + nj * 16, bcol));
                wlf[nj * 2][0] = r[0]; wlf[nj * 2][1] = r[1];
                wlf[nj * 2 + 1][0] = r[2]; wlf[nj * 2 + 1][1] = r[3];
            }
#pragma unroll
            for (int mi = 0; mi < 4; mi++)
#pragma unroll
                for (int ni = 0; ni < 4; ni++) {
                    mma_bf16(acc[mi][ni], af[mi], whf[ni]);
                    mma_bf16(acc[mi][ni], af[mi], wlf[ni]);
                }
#pragma unroll
            for (int mi = 0; mi < 4; mi++)
                ldsm_x4(af[mi], sb + ARR_A_L + swz(arow + mi * 16, acol));
#pragma unroll
            for (int mi = 0; mi < 4; mi++)
#pragma unroll
                for (int ni = 0; ni < 4; ni++)
                    mma_bf16(acc[mi][ni], af[mi], whf[ni]);
        }
    }

#pragma unroll
    for (int mi = 0; mi < 4; mi++) {
        int r0 = m0 + wm + mi * 16 + (lane >> 2);
#pragma unroll
        for (int ni = 0; ni < 4; ni++) {
            int c = n0 + wn + ni * 8 + (lane & 3) * 2;
            float2 v0 = make_float2(acc[mi][ni][0], acc[mi][ni][1]);
            float2 v1 = make_float2(acc[mi][ni][2], acc[mi][ni][3]);
            if (EPI == 2) {
                float b0 = bias[r0], b1 = bias[r0 + 8];
                v0.x = softplus_f(v0.x + b0); v0.y = softplus_f(v0.y + b0);
                v1.x = softplus_f(v1.x + b1); v1.y = softplus_f(v1.y + b1);
            }
            *(float2*)&Cout[(size_t)r0 * ldc + c] = v0;
            *(float2*)&Cout[(size_t)(r0 + 8) * ldc + c] = v1;
        }
    }
}

// ---------------------------------------------------------------------------
// x_proj reduce (column-pair threads): i over TT*48.
// col48 < 32  -> dtA col-pair (2*col48, 2*col48+1), bf16x2 stores
// col48 >= 32 -> BC pair j = 2*(col48-32), float2 store
// ---------------------------------------------------------------------------
__global__ void __launch_bounds__(256)
xred_kernel() {
    int i = blockIdx.x * 256 + threadIdx.x;
    if (i >= TT * 48) return;
    int col = i % 48;
    int row = i / 48;
    if (col < 32) {
        int c0 = col * 2;
        float v0 = 0.f, v1 = 0.f;
        if (c0 < DRR) {
            size_t s0 = (size_t)row * NRP + c0;
#pragma unroll
            for (int k = 0; k < XK; k++) {
                v0 += g_xp_part[k][s0];
                v1 += g_xp_part[k][s0 + 1];
            }
        }
        split_store2(v0, v1, g_dtA_h, g_dtA_l, (size_t)row * DTK + c0);
    } else {
        int j = (col - 32) * 2;               // 0,2,..,30
        size_t src = (size_t)row * NRP + DRR + j;
        float v0 = 0.f, v1 = 0.f;
#pragma unroll
        for (int k = 0; k < XK; k++) {
            v0 += g_xp_part[k][src];
            v1 += g_xp_part[k][src + 1];
        }
        *(float2*)&g_dbcBC[(size_t)row * 32 + j] = make_float2(v0, v1);
    }
}

// ---------------------------------------------------------------------------
// Causal depthwise conv: thread = 4 channels x 4 consecutive t (row reuse).
// ---------------------------------------------------------------------------
__global__ void __launch_bounds__(256)
conv_kernel(const float* __restrict__ xz, float* __restrict__ xc,
            __nv_bfloat16* __restrict__ xch, __nv_bfloat16* __restrict__ xcl,
            const float* __restrict__ cw, const float* __restrict__ cb) {
    int idx = blockIdx.x * blockDim.x + threadIdx.x;
    if (idx >= (TT / 4) * (DIN / 4)) return;
    int c4 = (idx % (DIN / 4)) * 4;
    int tb4 = idx / (DIN / 4);
    int t0 = (tb4 % (LL / 4)) * 4;
    int b = tb4 / (LL / 4);

    float4 wv[4];
#pragma unroll
    for (int j = 0; j < 4; j++)
        wv[j] = *(const float4*)(cw + (c4 + j) * KCC);
    const float w_[4][4] = {{wv[0].x, wv[0].y, wv[0].z, wv[0].w},
                            {wv[1].x, wv[1].y, wv[1].z, wv[1].w},
                            {wv[2].x, wv[2].y, wv[2].z, wv[2].w},
                            {wv[3].x, wv[3].y, wv[3].z, wv[3].w}};
    float4 bias = *(const float4*)(cb + c4);

    float4 xr[7];
#pragma unroll
    for (int r = 0; r < 7; r++) {
        int tt = t0 - 3 + r;
        if (tt >= 0)
            xr[r] = *(const float4*)(xz + ((size_t)(b * LL + tt)) * (2 * DIN) + c4);
        else
            xr[r] = make_float4(0.f, 0.f, 0.f, 0.f);
    }

#pragma unroll
    for (int j = 0; j < 4; j++) {
        float4 acc = bias;
#pragma unroll
        for (int k = 0; k < KCC; k++) {
            float4 xv = xr[j + k];
            acc.x += w_[0][k] * xv.x;
            acc.y += w_[1][k] * xv.y;
            acc.z += w_[2][k] * xv.z;
            acc.w += w_[3][k] * xv.w;
        }
        acc.x = acc.x / (1.f + __expf(-acc.x));
        acc.y = acc.y / (1.f + __expf(-acc.y));
        acc.z = acc.z / (1.f + __expf(-acc.z));
        acc.w = acc.w / (1.f + __expf(-acc.w));
        size_t o = ((size_t)(b * LL + t0 + j)) * DIN + c4;
        *(float4*)(xc + o) = acc;
        split_store4(acc, xch, xcl, o);
    }
}

// ===========================================================================
// Chunked selective scan (2 kernels), CH=16, CS=64.
// dtT[d][t] transposed; B/C from compact dbcBC. p2 computes h_init inline.
// ===========================================================================
__global__ void __launch_bounds__(256)
scan_p1_kernel(const float* __restrict__ dtT, const float* __restrict__ xc,
               const float* __restrict__ Alog) {
    int warp = threadIdx.x >> 5;
    int lane = threadIdx.x & 31;
    int n = lane & 15;
    int dl = lane >> 4;
    constexpr int BLOCKS_PER_B = DIN / 16;
    int b = blockIdx.x / BLOCKS_PER_B;
    int d = (blockIdx.x % BLOCKS_PER_B) * 16 + warp * 2 + dl;
    int c = blockIdx.y;

    float Av = -__expf(Alog[d * NSS + n]);
    float h = 0.f, sdt = 0.f;
    size_t rowbase = (size_t)b * LL + (size_t)c * CS;
    const float* dtp = dtT + (size_t)d * TT + rowbase;

    for (int t4 = 0; t4 < CS; t4 += 4) {
        float4 dv4 = *(const float4*)(dtp + t4);
        float dvv[4] = {dv4.x, dv4.y, dv4.z, dv4.w};
#pragma unroll
        for (int j = 0; j < 4; j++) {
            size_t row = rowbase + t4 + j;
            float dtv = dvv[j];
            float xv  = xc[row * DIN + d];
            float Bv  = g_dbcBC[row * 32 + n];
            sdt += dtv;
            h = __expf(dtv * Av) * h + (dtv * xv) * Bv;
        }
    }
    int idx = (b * DIN + d) * NSS + n;
    g_hend[(size_t)c * NSTATE + idx] = h;
    g_P[(size_t)c * NSTATE + idx]   = __expf(Av * sdt);
}

__global__ void __launch_bounds__(256)
scan_p2_kernel(const float* __restrict__ dtT, const float* __restrict__ xc,
               const float* __restrict__ xz,
               __nv_bfloat16* __restrict__ yh, __nv_bfloat16* __restrict__ yl,
               const float* __restrict__ Alog, const float* __restrict__ Dp) {
    int warp = threadIdx.x >> 5;
    int lane = threadIdx.x & 31;
    int n = lane & 15;
    int dl = lane >> 4;
    constexpr int BLOCKS_PER_B = DIN / 16;
    int b = blockIdx.x / BLOCKS_PER_B;
    int d = (blockIdx.x % BLOCKS_PER_B) * 16 + warp * 2 + dl;
    int c = blockIdx.y;

    float Av = -__expf(Alog[d * NSS + n]);
    float Dv = Dp[d];
    int idx = (b * DIN + d) * NSS + n;

    float h = 0.f;
    for (int cc = 0; cc < c; cc++) {
        h = g_P[(size_t)cc * NSTATE + idx] * h +
            g_hend[(size_t)cc * NSTATE + idx];
    }

    size_t rowbase = (size_t)b * LL + (size_t)c * CS;
    const float* dtp = dtT + (size_t)d * TT + rowbase;

    for (int t4 = 0; t4 < CS; t4 += 4) {
        float4 dv4 = *(const float4*)(dtp + t4);
        float dvv[4] = {dv4.x, dv4.y, dv4.z, dv4.w};
#pragma unroll
        for (int j = 0; j < 4; j++) {
            size_t row = rowbase + t4 + j;
            float dtv = dvv[j];
            float xv  = xc[row * DIN + d];
            float Bv  = g_dbcBC[row * 32 + n];
            float Cv  = g_dbcBC[row * 32 + 16 + n];
            h = __expf(dtv * Av) * h + (dtv * xv) * Bv;
            float yp = h * Cv;
            yp += __shfl_xor_sync(0xffffffffu, yp, 8);
            yp += __shfl_xor_sync(0xffffffffu, yp, 4);
            yp += __shfl_xor_sync(0xffffffffu, yp, 2);
            yp += __shfl_xor_sync(0xffffffffu, yp, 1);
            if (n == 0) {
                float zv = xz[row * (2 * DIN) + DIN + d];
                float sg = zv / (1.f + __expf(-zv));
                float g = (yp + xv * Dv) * sg;
                __nv_bfloat16 gh = __float2bfloat16(g);
                yh[row * DIN + d] = gh;
                yl[row * DIN + d] = __float2bfloat16(g - __bfloat162float(gh));
            }
        }
    }
}

// ---------------------------------------------------------------------------
// Orchestration
// ---------------------------------------------------------------------------
extern "C" void kernel_launch(void* const* d_in, const int* in_sizes, int n_in,
                              void* d_out, int out_size) {
    const float* x        = (const float*)d_in[0];
    const float* ln_w     = (const float*)d_in[1];
    const float* ln_b     = (const float*)d_in[2];
    const float* in_proj  = (const float*)d_in[3];
    const float* conv_w   = (const float*)d_in[4];
    const float* conv_b   = (const float*)d_in[5];
    const float* x_proj   = (const float*)d_in[6];
    const float* dt_w     = (const float*)d_in[7];
    const float* dt_b     = (const float*)d_in[8];
    const float* A_log    = (const float*)d_in[9];
    const float* D_skip   = (const float*)d_in[10];
    const float* out_proj = (const float*)d_in[11];
    const float* fn_w     = (const float*)d_in[12];
    const float* fn_b     = (const float*)d_in[13];
    float* out = (float*)d_out;

    float* base = nullptr;
    cudaGetSymbolAddress((void**)&base, g_buf);
    float* bres = base + O_RES;
    float* bxz  = base + O_XZ;
    float* bxc  = base + O_XC;
    float* bdt  = base + O_DT;

    __nv_bfloat16 *xnh, *xnl, *yh, *yl, *xch, *xcl, *dtah, *dtal;
    __nv_bfloat16 *wih, *wil, *woh, *wol, *wxh, *wxl, *wdh, *wdl;
    cudaGetSymbolAddress((void**)&xnh, g_xn_h);
    cudaGetSymbolAddress((void**)&xnl, g_xn_l);
    cudaGetSymbolAddress((void**)&yh,  g_y_h);
    cudaGetSymbolAddress((void**)&yl,  g_y_l);
    cudaGetSymbolAddress((void**)&xch, g_xc_h);
    cudaGetSymbolAddress((void**)&xcl, g_xc_l);
    cudaGetSymbolAddress((void**)&dtah, g_dtA_h);
    cudaGetSymbolAddress((void**)&dtal, g_dtA_l);
    cudaGetSymbolAddress((void**)&wih, g_wi_h);
    cudaGetSymbolAddress((void**)&wil, g_wi_l);
    cudaGetSymbolAddress((void**)&woh, g_wo_h);
    cudaGetSymbolAddress((void**)&wol, g_wo_l);
    cudaGetSymbolAddress((void**)&wxh, g_wx_h);
    cudaGetSymbolAddress((void**)&wxl, g_wx_l);
    cudaGetSymbolAddress((void**)&wdh, g_wdt_h);
    cudaGetSymbolAddress((void**)&wdl, g_wdt_l);

    float *xfpart, *xppart;
    cudaGetSymbolAddress((void**)&xfpart, g_xf_part);
    cudaGetSymbolAddress((void**)&xppart, g_xp_part);

    cudaFuncSetAttribute(gemm_tc2_kernel<0>,
                         cudaFuncAttributeMaxDynamicSharedMemorySize,
                         NSTAGE * STAGE_BYTES);
    cudaFuncSetAttribute(gemm_tc2_kernel<2>,
                         cudaFuncAttributeMaxDynamicSharedMemorySize,
                         NSTAGE * STAGE_BYTES);

    size_t ncvt = NWI + NWO + NWX + NWDT;
    cvt_weights_kernel<<<(unsigned)((ncvt + 255) / 256), 256>>>(
        in_proj, out_proj, x_proj, dt_w);
    ln_kernel<0><<<TT, 192>>>(x, bres, xnh, xnl, ln_w, ln_b, nullptr);

    for (int l = 0; l < NLAY; l++) {
        // xz = xn @ Wi^T   (2048 x 3072, K=768)
        gemm_tc2_kernel<0><<<dim3((2 * DIN) / 128, TT / 128, 1), 256,
                             NSTAGE * STAGE_BYTES>>>(
            xnh, xnl,
            wih + (size_t)l * 2 * DIN * DD, wil + (size_t)l * 2 * DIN * DD,
            nullptr, bxz, 2 * DIN, DD, DD, 0);
        // xc = silu(conv(xi) + cb)
        conv_kernel<<<((TT / 4) * (DIN / 4)) / 256, 256>>>(
            bxz, bxc, xch, xcl,
            conv_w + (size_t)l * DIN * KCC, conv_b + (size_t)l * DIN);
        // dbc partials = xc @ Wx^T  (TC, N padded 128, split-K x8)
        gemm_tc2_kernel<0><<<dim3(1, TT / 128, XK), 256,
                             NSTAGE * STAGE_BYTES>>>(
            xch, xcl,
            wxh + (size_t)l * NRP * DIN, wxl + (size_t)l * NRP * DIN,
            nullptr, xppart, NRP, XKS, DIN, (size_t)TT * NRP);
        // reduce -> dtA bf16 hi/lo + compact dbcBC (pair threads)
        xred_kernel<<<(TT * 48 + 255) / 256, 256>>>();
        // dtT[d][t] = softplus(Wdt @ dtA^T + bdt)
        gemm_tc2_kernel<2><<<dim3(TT / 128, DIN / 128, 1), 256,
                             NSTAGE * STAGE_BYTES>>>(
            wdh + (size_t)l * DIN * DTK, wdl + (size_t)l * DIN * DTK,
            dtah, dtal,
            dt_b + (size_t)l * DIN, bdt, TT, DTK, DTK, 0);
        // chunked selective scan (p2 does the chain inline)
        scan_p1_kernel<<<dim3(BB * (DIN / 16), CH), 256>>>(
            bdt, bxc, A_log + (size_t)l * DIN * NSS);
        scan_p2_kernel<<<dim3(BB * (DIN / 16), CH), 256>>>(
            bdt, bxc, bxz, yh, yl,
            A_log + (size_t)l * DIN * NSS, D_skip + (size_t)l * DIN);
        // x_next partials = y @ Wo^T  split-K x3
        gemm_tc2_kernel<0><<<dim3(DD / 128, TT / 128, OK), 256,
                             NSTAGE * STAGE_BYTES>>>(
            yh, yl,
            woh + (size_t)l * DD * DIN, wol + (size_t)l * DD * DIN,
            nullptr, xfpart, DD, OKS, DIN, (size_t)TT * DD);
        // fused reduce + LN (next layer) or final LN
        if (l + 1 < NLAY) {
            ln_kernel<1><<<TT, 192>>>(nullptr, bres, xnh, xnl,
                                      ln_w + (size_t)(l + 1) * DD,
                                      ln_b + (size_t)(l + 1) * DD, nullptr);
        } else {
            ln_kernel<2><<<TT, 192>>>(nullptr, bres, nullptr, nullptr,
                                      fn_w, fn_b, out);
        }
    }
}

// round 16
// speedup vs baseline: 1.0195x; 1.0195x over previous
#include <cuda_runtime.h>
#include <cuda_bf16.h>
#include <math.h>
#include <stdint.h>

// Problem constants
constexpr int BB   = 2;
constexpr int LL   = 1024;
constexpr int DD   = 768;
constexpr int NLAY = 8;
constexpr int DIN  = 1536;       // 2*D
constexpr int NSS  = 16;
constexpr int DRR  = 48;         // D/16
constexpr int KCC  = 4;
constexpr int TT   = BB * LL;    // 2048 tokens
constexpr int NR   = DRR + 2 * NSS;  // 80 (logical)
constexpr int NRP  = 128;        // padded x_proj partial row stride

// Chunked scan
constexpr int CH = 16;
constexpr int CS = LL / CH;      // 64
constexpr int NSTATE = BB * DIN * NSS;   // 49152

// split-K factors
constexpr int XK = 8;            // x_proj
constexpr int XKS = DIN / XK;    // 192
constexpr int OK = 3;            // out_proj
constexpr int OKS = DIN / OK;    // 512
constexpr int DTK = 64;          // dt padded K

// fp32 scratch
constexpr size_t O_RES = 0;
constexpr size_t O_XZ  = O_RES + (size_t)TT * DD;
constexpr size_t O_XC  = O_XZ  + (size_t)TT * 2 * DIN;
constexpr size_t O_DT  = O_XC  + (size_t)TT * DIN;   // dtT [DIN][TT]
constexpr size_t O_END = O_DT  + (size_t)DIN * TT;
__device__ float g_buf[O_END];

__device__ float g_hend[(size_t)CH * NSTATE];
__device__ float g_P[(size_t)CH * NSTATE];
__device__ float g_xf_part[OK][(size_t)TT * DD];
__device__ float g_xp_part[XK][(size_t)TT * NRP];
__device__ float g_dbcBC[(size_t)TT * 32];       // [t][0..15]=B, [16..31]=C

// bf16 hi/lo activation + weight buffers
constexpr size_t NWI  = (size_t)NLAY * 2 * DIN * DD;
constexpr size_t NWO  = (size_t)NLAY * DD * DIN;
constexpr size_t NWX  = (size_t)NLAY * NRP * DIN;
constexpr size_t NWDT = (size_t)NLAY * DIN * DTK;
__device__ __nv_bfloat16 g_xn_h[(size_t)TT * DD];
__device__ __nv_bfloat16 g_xn_l[(size_t)TT * DD];
__device__ __nv_bfloat16 g_y_h[(size_t)TT * DIN];
__device__ __nv_bfloat16 g_y_l[(size_t)TT * DIN];
__device__ __nv_bfloat16 g_xc_h[(size_t)TT * DIN];
__device__ __nv_bfloat16 g_xc_l[(size_t)TT * DIN];
__device__ __nv_bfloat16 g_dtA_h[(size_t)TT * DTK];
__device__ __nv_bfloat16 g_dtA_l[(size_t)TT * DTK];
__device__ __nv_bfloat16 g_wi_h[NWI];
__device__ __nv_bfloat16 g_wi_l[NWI];
__device__ __nv_bfloat16 g_wo_h[NWO];
__device__ __nv_bfloat16 g_wo_l[NWO];
__device__ __nv_bfloat16 g_wx_h[NWX];
__device__ __nv_bfloat16 g_wx_l[NWX];
__device__ __nv_bfloat16 g_wdt_h[NWDT];
__device__ __nv_bfloat16 g_wdt_l[NWDT];

// ---------------------------------------------------------------------------
// helpers
// ---------------------------------------------------------------------------
__device__ __forceinline__ void split_store(float v, __nv_bfloat16* H,
                                            __nv_bfloat16* L, size_t i) {
    __nv_bfloat16 h = __float2bfloat16(v);
    H[i] = h;
    L[i] = __float2bfloat16(v - __bfloat162float(h));
}

// packed 4-wide split store (i must be 2-aligned; values identical to
// elementwise split_store since both use round-to-nearest)
__device__ __forceinline__ void split_store4(float4 v, __nv_bfloat16* H,
                                             __nv_bfloat16* L, size_t i) {
    __nv_bfloat162 h0 = __floats2bfloat162_rn(v.x, v.y);
    __nv_bfloat162 h1 = __floats2bfloat162_rn(v.z, v.w);
    __nv_bfloat162 l0 = __floats2bfloat162_rn(v.x - __low2float(h0),
                                              v.y - __high2float(h0));
    __nv_bfloat162 l1 = __floats2bfloat162_rn(v.z - __low2float(h1),
                                              v.w - __high2float(h1));
    *reinterpret_cast<__nv_bfloat162*>(H + i)     = h0;
    *reinterpret_cast<__nv_bfloat162*>(H + i + 2) = h1;
    *reinterpret_cast<__nv_bfloat162*>(L + i)     = l0;
    *reinterpret_cast<__nv_bfloat162*>(L + i + 2) = l1;
}

__global__ void cvt_weights_kernel(const float* __restrict__ wi,
                                   const float* __restrict__ wo,
                                   const float* __restrict__ wx,
                                   const float* __restrict__ wdt) {
    size_t i = (size_t)blockIdx.x * 256 + threadIdx.x;
    if (i < NWI) { split_store(wi[i], g_wi_h, g_wi_l, i); return; }
    i -= NWI;
    if (i < NWO) { split_store(wo[i], g_wo_h, g_wo_l, i); return; }
    i -= NWO;
    if (i < NWX) {
        size_t k = i % DIN;
        size_t r = (i / DIN) % NRP;
        size_t l = i / ((size_t)DIN * NRP);
        float v = (r < NR) ? wx[(l * NR + r) * DIN + k] : 0.f;
        split_store(v, g_wx_h, g_wx_l, i);
        return;
    }
    i -= NWX;
    if (i < NWDT) {
        size_t k = i % DTK;
        size_t d = (i / DTK) % DIN;
        size_t l = i / ((size_t)DTK * DIN);
        float v = (k < DRR) ? wdt[(l * DIN + d) * DRR + k] : 0.f;
        split_store(v, g_wdt_h, g_wdt_l, i);
    }
}

__device__ __forceinline__ float block_sum_256(float v, float* red,
                                               int lane, int wid) {
#pragma unroll
    for (int o = 16; o > 0; o >>= 1)
        v += __shfl_xor_sync(0xffffffffu, v, o);
    if (lane == 0) red[wid] = v;
    __syncthreads();
    return red[0] + red[1] + red[2] + red[3] +
           red[4] + red[5] + red[6] + red[7];
}

__device__ __forceinline__ void ln_emit(float d0, float d1, float d2, float inv,
                                        int tid, size_t rowoff,
                                        const float* __restrict__ w,
                                        const float* __restrict__ b,
                                        __nv_bfloat16* __restrict__ xnh,
                                        __nv_bfloat16* __restrict__ xnl) {
#pragma unroll
    for (int c = 0; c < 3; c++) {
        int i = tid + c * 256;
        float dv = (c == 0 ? d0 : c == 1 ? d1 : d2);
        float v = dv * inv * w[i] + b[i];
        __nv_bfloat16 h = __float2bfloat16(v);
        xnh[rowoff + i] = h;
        xnl[rowoff + i] = __float2bfloat16(v - __bfloat162float(h));
    }
}

// ---------------------------------------------------------------------------
// Layer-0 LN
// ---------------------------------------------------------------------------
__global__ void __launch_bounds__(256)
ln_first_kernel(const float* __restrict__ x, float* __restrict__ res,
                __nv_bfloat16* __restrict__ xnh, __nv_bfloat16* __restrict__ xnl,
                const float* __restrict__ w, const float* __restrict__ b) {
    int row = blockIdx.x;
    size_t ro = (size_t)row * DD;
    int tid = threadIdx.x;
    int lane = tid & 31, wid = tid >> 5;
    __shared__ float red[8];

    float v0 = x[ro + tid], v1 = x[ro + tid + 256], v2 = x[ro + tid + 512];
    float mu = block_sum_256(v0 + v1 + v2, red, lane, wid) * (1.f / DD);
    __syncthreads();
    float d0 = v0 - mu, d1 = v1 - mu, d2 = v2 - mu;
    float var = block_sum_256(d0 * d0 + d1 * d1 + d2 * d2, red, lane, wid)
                * (1.f / DD);
    float inv = rsqrtf(var + 1e-5f);
    ln_emit(d0, d1, d2, inv, tid, ro, w, b, xnh, xnl);
    res[ro + tid]       = v0;
    res[ro + tid + 256] = v1;
    res[ro + tid + 512] = v2;
}

// ---------------------------------------------------------------------------
// Fused out_proj reduce + next-layer LN
// ---------------------------------------------------------------------------
__global__ void __launch_bounds__(256)
ln_fuse_kernel(float* __restrict__ res,
               __nv_bfloat16* __restrict__ xnh, __nv_bfloat16* __restrict__ xnl,
               const float* __restrict__ w, const float* __restrict__ b) {
    int row = blockIdx.x;
    size_t ro = (size_t)row * DD;
    int tid = threadIdx.x;
    int lane = tid & 31, wid = tid >> 5;
    __shared__ float red[8];

    float v0 = g_xf_part[0][ro + tid] + g_xf_part[1][ro + tid] +
               g_xf_part[2][ro + tid];
    float v1 = g_xf_part[0][ro + tid + 256] + g_xf_part[1][ro + tid + 256] +
               g_xf_part[2][ro + tid + 256];
    float v2 = g_xf_part[0][ro + tid + 512] + g_xf_part[1][ro + tid + 512] +
               g_xf_part[2][ro + tid + 512];
    float mu = block_sum_256(v0 + v1 + v2, red, lane, wid) * (1.f / DD);
    __syncthreads();
    float d0 = v0 - mu, d1 = v1 - mu, d2 = v2 - mu;
    float var = block_sum_256(d0 * d0 + d1 * d1 + d2 * d2, red, lane, wid)
                * (1.f / DD);
    float inv = rsqrtf(var + 1e-5f);
    ln_emit(d0, d1, d2, inv, tid, ro, w, b, xnh, xnl);
    res[ro + tid]       += v0;
    res[ro + tid + 256] += v1;
    res[ro + tid + 512] += v2;
}

__global__ void __launch_bounds__(256)
final_fuse_kernel(const float* __restrict__ res,
                  const float* __restrict__ w, const float* __restrict__ b,
                  float* __restrict__ out) {
    int row = blockIdx.x;
    size_t ro = (size_t)row * DD;
    int tid = threadIdx.x;
    int lane = tid & 31, wid = tid >> 5;
    __shared__ float red[8];

    float v0 = g_xf_part[0][ro + tid] + g_xf_part[1][ro + tid] +
               g_xf_part[2][ro + tid] + res[ro + tid];
    float v1 = g_xf_part[0][ro + tid + 256] + g_xf_part[1][ro + tid + 256] +
               g_xf_part[2][ro + tid + 256] + res[ro + tid + 256];
    float v2 = g_xf_part[0][ro + tid + 512] + g_xf_part[1][ro + tid + 512] +
               g_xf_part[2][ro + tid + 512] + res[ro + tid + 512];
    float mu = block_sum_256(v0 + v1 + v2, red, lane, wid) * (1.f / DD);
    __syncthreads();
    float d0 = v0 - mu, d1 = v1 - mu, d2 = v2 - mu;
    float var = block_sum_256(d0 * d0 + d1 * d1 + d2 * d2, red, lane, wid)
                * (1.f / DD);
    float inv = rsqrtf(var + 1e-5f);
    out[ro + tid]       = d0 * inv * w[tid]       + b[tid];
    out[ro + tid + 256] = d1 * inv * w[tid + 256] + b[tid + 256];
    out[ro + tid + 512] = d2 * inv * w[tid + 512] + b[tid + 512];
}

// ===========================================================================
// Tensor-core GEMM (bf16 hi/lo, 3-pass), optional split-K + epilogue.
// EPI 0: plain.  EPI 2: bias[row] + softplus (transposed dt GEMM).
// ===========================================================================
__device__ __forceinline__ unsigned smem_u32(const void* p) {
    return (unsigned)__cvta_generic_to_shared(p);
}
__device__ __forceinline__ unsigned swz(int r, int c) {
    return (unsigned)(r * 64) + ((((unsigned)c >> 3) ^ (((unsigned)r >> 1) & 3u)) << 4);
}
__device__ __forceinline__ void ldsm_x4(unsigned* r, unsigned addr) {
    asm volatile("ldmatrix.sync.aligned.m8n8.x4.shared.b16 {%0,%1,%2,%3}, [%4];"
                 : "=r"(r[0]), "=r"(r[1]), "=r"(r[2]), "=r"(r[3]) : "r"(addr));
}
__device__ __forceinline__ void mma_bf16(float* c, const unsigned* a, const unsigned* b) {
    asm volatile(
        "mma.sync.aligned.m16n8k16.row.col.f32.bf16.bf16.f32 "
        "{%0,%1,%2,%3}, {%4,%5,%6,%7}, {%8,%9}, {%0,%1,%2,%3};"
        : "+f"(c[0]), "+f"(c[1]), "+f"(c[2]), "+f"(c[3])
        : "r"(a[0]), "r"(a[1]), "r"(a[2]), "r"(a[3]), "r"(b[0]), "r"(b[1]));
}
__device__ __forceinline__ void cp16(unsigned dst, const void* src) {
    asm volatile("cp.async.cg.shared.global [%0], [%1], 16;" :: "r"(dst), "l"(src));
}
__device__ __forceinline__ float softplus_f(float v) {
    return (v > 20.f) ? v : log1pf(__expf(v));
}

constexpr int STAGE_BYTES = 32768;
constexpr int NSTAGE = 3;
constexpr int ARR_A_H = 0, ARR_A_L = 8192, ARR_W_H = 16384, ARR_W_L = 24576;

template <int EPI>
__global__ void __launch_bounds__(256)
gemm_tc2_kernel(const __nv_bfloat16* __restrict__ Ahg,
                const __nv_bfloat16* __restrict__ Alg,
                const __nv_bfloat16* __restrict__ Whg,
                const __nv_bfloat16* __restrict__ Wlg,
                const float* __restrict__ bias,
                float* __restrict__ C, int ldc,
                int Ksplit, int Kfull, size_t partStride) {
    extern __shared__ __align__(16) unsigned char smraw[];
    const unsigned sbase = smem_u32(smraw);

    const int tid  = threadIdx.x;
    const int lane = tid & 31;
    const int warp = tid >> 5;
    const int wm = (warp & 1) * 64;
    const int wn = (warp >> 1) * 32;
    const int m0 = blockIdx.y * 128;
    const int n0 = blockIdx.x * 128;
    const int koff = blockIdx.z * Ksplit;
    float* Cout = C + (size_t)blockIdx.z * partStride;

    const int lrow = tid >> 1;
    const int lq0  = (tid & 1) * 2;
    const size_t aoff = (size_t)(m0 + lrow) * Kfull + koff;
    const size_t woff = (size_t)(n0 + lrow) * Kfull + koff;
    const unsigned sdst0 = (unsigned)(lrow * 64) +
                           (((unsigned)lq0 ^ (((unsigned)lrow >> 1) & 3u)) << 4);
    const unsigned sdst1 = (unsigned)(lrow * 64) +
                           ((((unsigned)lq0 + 1u) ^ (((unsigned)lrow >> 1) & 3u)) << 4);

    const int nsteps = Ksplit / 32;

    auto load_stage = [&](int buf, int k0) {
        unsigned sb = sbase + buf * STAGE_BYTES;
        const __nv_bfloat16* pa_h = Ahg + aoff + k0 + lq0 * 8;
        const __nv_bfloat16* pa_l = Alg + aoff + k0 + lq0 * 8;
        const __nv_bfloat16* pw_h = Whg + woff + k0 + lq0 * 8;
        const __nv_bfloat16* pw_l = Wlg + woff + k0 + lq0 * 8;
        cp16(sb + ARR_A_H + sdst0, pa_h);
        cp16(sb + ARR_A_H + sdst1, pa_h + 8);
        cp16(sb + ARR_A_L + sdst0, pa_l);
        cp16(sb + ARR_A_L + sdst1, pa_l + 8);
        cp16(sb + ARR_W_H + sdst0, pw_h);
        cp16(sb + ARR_W_H + sdst1, pw_h + 8);
        cp16(sb + ARR_W_L + sdst0, pw_l);
        cp16(sb + ARR_W_L + sdst1, pw_l + 8);
    };

    float acc[4][4][4];
#pragma unroll
    for (int i = 0; i < 4; i++)
#pragma unroll
        for (int j = 0; j < 4; j++)
#pragma unroll
            for (int q = 0; q < 4; q++) acc[i][j][q] = 0.f;

    load_stage(0, 0);
    asm volatile("cp.async.commit_group;");
    if (nsteps > 1) load_stage(1, 32);
    asm volatile("cp.async.commit_group;");

    const int arow = wm + (lane & 7) + (lane & 8);
    const int brow = wn + (lane & 7) + ((lane >> 4) << 3);

    for (int s = 0; s < nsteps; s++) {
        asm volatile("cp.async.wait_group 1;");
        __syncthreads();
        if (s + 2 < nsteps) load_stage((s + 2) % NSTAGE, (s + 2) * 32);
        asm volatile("cp.async.commit_group;");

        const unsigned sb = sbase + (s % NSTAGE) * STAGE_BYTES;
#pragma unroll
        for (int kk = 0; kk < 32; kk += 16) {
            const int acol = kk + ((lane >> 4) << 3);
            const int bcol = kk + (lane & 8);
            unsigned af[4][4];
            unsigned whf[4][2], wlf[4][2];
#pragma unroll
            for (int mi = 0; mi < 4; mi++)
                ldsm_x4(af[mi], sb + ARR_A_H + swz(arow + mi * 16, acol));
#pragma unroll
            for (int nj = 0; nj < 2; nj++) {
                unsigned r[4];
                ldsm_x4(r, sb + ARR_W_H + swz(brow + nj * 16, bcol));
                whf[nj * 2][0] = r[0]; whf[nj * 2][1] = r[1];
                whf[nj * 2 + 1][0] = r[2]; whf[nj * 2 + 1][1] = r[3];
                ldsm_x4(r, sb + ARR_W_L + swz(brow + nj * 16, bcol));
                wlf[nj * 2][0] = r[0]; wlf[nj * 2][1] = r[1];
                wlf[nj * 2 + 1][0] = r[2]; wlf[nj * 2 + 1][1] = r[3];
            }
#pragma unroll
            for (int mi = 0; mi < 4; mi++)
#pragma unroll
                for (int ni = 0; ni < 4; ni++) {
                    mma_bf16(acc[mi][ni], af[mi], whf[ni]);
                    mma_bf16(acc[mi][ni], af[mi], wlf[ni]);
                }
#pragma unroll
            for (int mi = 0; mi < 4; mi++)
                ldsm_x4(af[mi], sb + ARR_A_L + swz(arow + mi * 16, acol));
#pragma unroll
            for (int mi = 0; mi < 4; mi++)
#pragma unroll
                for (int ni = 0; ni < 4; ni++)
                    mma_bf16(acc[mi][ni], af[mi], whf[ni]);
        }
    }

#pragma unroll
    for (int mi = 0; mi < 4; mi++) {
        int r0 = m0 + wm + mi * 16 + (lane >> 2);
#pragma unroll
        for (int ni = 0; ni < 4; ni++) {
            int c = n0 + wn + ni * 8 + (lane & 3) * 2;
            float2 v0 = make_float2(acc[mi][ni][0], acc[mi][ni][1]);
            float2 v1 = make_float2(acc[mi][ni][2], acc[mi][ni][3]);
            if (EPI == 2) {
                float b0 = bias[r0], b1 = bias[r0 + 8];
                v0.x = softplus_f(v0.x + b0); v0.y = softplus_f(v0.y + b0);
                v1.x = softplus_f(v1.x + b1); v1.y = softplus_f(v1.y + b1);
            }
            *(float2*)&Cout[(size_t)r0 * ldc + c] = v0;
            *(float2*)&Cout[(size_t)(r0 + 8) * ldc + c] = v1;
        }
    }
}

// ---------------------------------------------------------------------------
// x_proj reduce: sum XK partials over used cols only.
// ---------------------------------------------------------------------------
__global__ void __launch_bounds__(256)
xred_kernel() {
    int i = blockIdx.x * 256 + threadIdx.x;
    if (i >= TT * 96) return;
    int col = i % 96;
    int row = i / 96;
    if (col < DTK) {
        float v = 0.f;
        if (col < DRR) {
            size_t src = (size_t)row * NRP + col;
#pragma unroll
            for (int k = 0; k < XK; k++) v += g_xp_part[k][src];
        }
        split_store(v, g_dtA_h, g_dtA_l, (size_t)row * DTK + col);
    } else {
        int j = col - 64;                     // 0..31
        size_t src = (size_t)row * NRP + DRR + j;
        float v = 0.f;
#pragma unroll
        for (int k = 0; k < XK; k++) v += g_xp_part[k][src];
        g_dbcBC[(size_t)row * 32 + j] = v;
    }
}

// ---------------------------------------------------------------------------
// Causal depthwise conv: thread = 4 channels x 4 consecutive t (row reuse).
// ---------------------------------------------------------------------------
__global__ void __launch_bounds__(256)
conv_kernel(const float* __restrict__ xz, float* __restrict__ xc,
            __nv_bfloat16* __restrict__ xch, __nv_bfloat16* __restrict__ xcl,
            const float* __restrict__ cw, const float* __restrict__ cb) {
    int idx = blockIdx.x * blockDim.x + threadIdx.x;   // over TT/4 * DIN/4
    if (idx >= (TT / 4) * (DIN / 4)) return;
    int c4 = (idx % (DIN / 4)) * 4;
    int tb4 = idx / (DIN / 4);
    int t0 = (tb4 % (LL / 4)) * 4;
    int b = tb4 / (LL / 4);

    float4 wv[4];
#pragma unroll
    for (int j = 0; j < 4; j++)
        wv[j] = *(const float4*)(cw + (c4 + j) * KCC);
    const float w_[4][4] = {{wv[0].x, wv[0].y, wv[0].z, wv[0].w},
                            {wv[1].x, wv[1].y, wv[1].z, wv[1].w},
                            {wv[2].x, wv[2].y, wv[2].z, wv[2].w},
                            {wv[3].x, wv[3].y, wv[3].z, wv[3].w}};
    float4 bias = *(const float4*)(cb + c4);

    // rows t0-3 .. t0+3
    float4 xr[7];
#pragma unroll
    for (int r = 0; r < 7; r++) {
        int tt = t0 - 3 + r;
        if (tt >= 0)
            xr[r] = *(const float4*)(xz + ((size_t)(b * LL + tt)) * (2 * DIN) + c4);
        else
            xr[r] = make_float4(0.f, 0.f, 0.f, 0.f);
    }

#pragma unroll
    for (int j = 0; j < 4; j++) {            // output t = t0 + j
        float4 acc = bias;
#pragma unroll
        for (int k = 0; k < KCC; k++) {
            float4 xv = xr[j + k];
            acc.x += w_[0][k] * xv.x;
            acc.y += w_[1][k] * xv.y;
            acc.z += w_[2][k] * xv.z;
            acc.w += w_[3][k] * xv.w;
        }
        acc.x = acc.x / (1.f + __expf(-acc.x));
        acc.y = acc.y / (1.f + __expf(-acc.y));
        acc.z = acc.z / (1.f + __expf(-acc.z));
        acc.w = acc.w / (1.f + __expf(-acc.w));
        size_t o = ((size_t)(b * LL + t0 + j)) * DIN + c4;
        *(float4*)(xc + o) = acc;
        split_store4(acc, xch, xcl, o);
    }
}

// ===========================================================================
// Chunked selective scan (2 kernels), CH=16, CS=64.
// dtT[d][t] transposed; B/C from compact dbcBC. p2 computes h_init inline.
// ===========================================================================
__global__ void __launch_bounds__(256)
scan_p1_kernel(const float* __restrict__ dtT, const float* __restrict__ xc,
               const float* __restrict__ Alog) {
    int warp = threadIdx.x >> 5;
    int lane = threadIdx.x & 31;
    int n = lane & 15;
    int dl = lane >> 4;
    constexpr int BLOCKS_PER_B = DIN / 16;
    int b = blockIdx.x / BLOCKS_PER_B;
    int d = (blockIdx.x % BLOCKS_PER_B) * 16 + warp * 2 + dl;
    int c = blockIdx.y;

    float Av = -__expf(Alog[d * NSS + n]);
    float h = 0.f, sdt = 0.f;
    size_t rowbase = (size_t)b * LL + (size_t)c * CS;
    const float* dtp = dtT + (size_t)d * TT + rowbase;

    for (int t4 = 0; t4 < CS; t4 += 4) {
        float4 dv4 = *(const float4*)(dtp + t4);
        float dvv[4] = {dv4.x, dv4.y, dv4.z, dv4.w};
#pragma unroll
        for (int j = 0; j < 4; j++) {
            size_t row = rowbase + t4 + j;
            float dtv = dvv[j];
            float xv  = xc[row * DIN + d];
            float Bv  = g_dbcBC[row * 32 + n];
            sdt += dtv;
            h = __expf(dtv * Av) * h + (dtv * xv) * Bv;
        }
    }
    int idx = (b * DIN + d) * NSS + n;
    g_hend[(size_t)c * NSTATE + idx] = h;
    g_P[(size_t)c * NSTATE + idx]   = __expf(Av * sdt);
}

__global__ void __launch_bounds__(256)
scan_p2_kernel(const float* __restrict__ dtT, const float* __restrict__ xc,
               const float* __restrict__ xz,
               __nv_bfloat16* __restrict__ yh, __nv_bfloat16* __restrict__ yl,
               const float* __restrict__ Alog, const float* __restrict__ Dp) {
    int warp = threadIdx.x >> 5;
    int lane = threadIdx.x & 31;
    int n = lane & 15;
    int dl = lane >> 4;
    constexpr int BLOCKS_PER_B = DIN / 16;
    int b = blockIdx.x / BLOCKS_PER_B;
    int d = (blockIdx.x % BLOCKS_PER_B) * 16 + warp * 2 + dl;
    int c = blockIdx.y;

    float Av = -__expf(Alog[d * NSS + n]);
    float Dv = Dp[d];
    int idx = (b * DIN + d) * NSS + n;

    // inline chain: h_init for chunk c
    float h = 0.f;
    for (int cc = 0; cc < c; cc++) {
        h = g_P[(size_t)cc * NSTATE + idx] * h +
            g_hend[(size_t)cc * NSTATE + idx];
    }

    size_t rowbase = (size_t)b * LL + (size_t)c * CS;
    const float* dtp = dtT + (size_t)d * TT + rowbase;

    for (int t4 = 0; t4 < CS; t4 += 4) {
        float4 dv4 = *(const float4*)(dtp + t4);
        float dvv[4] = {dv4.x, dv4.y, dv4.z, dv4.w};
#pragma unroll
        for (int j = 0; j < 4; j++) {
            size_t row = rowbase + t4 + j;
            float dtv = dvv[j];
            float xv  = xc[row * DIN + d];
            float Bv  = g_dbcBC[row * 32 + n];
            float Cv  = g_dbcBC[row * 32 + 16 + n];
            h = __expf(dtv * Av) * h + (dtv * xv) * Bv;
            float yp = h * Cv;
            yp += __shfl_xor_sync(0xffffffffu, yp, 8);
            yp += __shfl_xor_sync(0xffffffffu, yp, 4);
            yp += __shfl_xor_sync(0xffffffffu, yp, 2);
            yp += __shfl_xor_sync(0xffffffffu, yp, 1);
            if (n == 0) {
                float zv = xz[row * (2 * DIN) + DIN + d];
                float sg = zv / (1.f + __expf(-zv));
                float g = (yp + xv * Dv) * sg;
                __nv_bfloat16 gh = __float2bfloat16(g);
                yh[row * DIN + d] = gh;
                yl[row * DIN + d] = __float2bfloat16(g - __bfloat162float(gh));
            }
        }
    }
}

// ---------------------------------------------------------------------------
// Orchestration
// ---------------------------------------------------------------------------
extern "C" void kernel_launch(void* const* d_in, const int* in_sizes, int n_in,
                              void* d_out, int out_size) {
    const float* x        = (const float*)d_in[0];
    const float* ln_w     = (const float*)d_in[1];
    const float* ln_b     = (const float*)d_in[2];
    const float* in_proj  = (const float*)d_in[3];
    const float* conv_w   = (const float*)d_in[4];
    const float* conv_b   = (const float*)d_in[5];
    const float* x_proj   = (const float*)d_in[6];
    const float* dt_w     = (const float*)d_in[7];
    const float* dt_b     = (const float*)d_in[8];
    const float* A_log    = (const float*)d_in[9];
    const float* D_skip   = (const float*)d_in[10];
    const float* out_proj = (const float*)d_in[11];
    const float* fn_w     = (const float*)d_in[12];
    const float* fn_b     = (const float*)d_in[13];
    float* out = (float*)d_out;

    float* base = nullptr;
    cudaGetSymbolAddress((void**)&base, g_buf);
    float* bres = base + O_RES;
    float* bxz  = base + O_XZ;
    float* bxc  = base + O_XC;
    float* bdt  = base + O_DT;

    __nv_bfloat16 *xnh, *xnl, *yh, *yl, *xch, *xcl, *dtah, *dtal;
    __nv_bfloat16 *wih, *wil, *woh, *wol, *wxh, *wxl, *wdh, *wdl;
    cudaGetSymbolAddress((void**)&xnh, g_xn_h);
    cudaGetSymbolAddress((void**)&xnl, g_xn_l);
    cudaGetSymbolAddress((void**)&yh,  g_y_h);
    cudaGetSymbolAddress((void**)&yl,  g_y_l);
    cudaGetSymbolAddress((void**)&xch, g_xc_h);
    cudaGetSymbolAddress((void**)&xcl, g_xc_l);
    cudaGetSymbolAddress((void**)&dtah, g_dtA_h);
    cudaGetSymbolAddress((void**)&dtal, g_dtA_l);
    cudaGetSymbolAddress((void**)&wih, g_wi_h);
    cudaGetSymbolAddress((void**)&wil, g_wi_l);
    cudaGetSymbolAddress((void**)&woh, g_wo_h);
    cudaGetSymbolAddress((void**)&wol, g_wo_l);
    cudaGetSymbolAddress((void**)&wxh, g_wx_h);
    cudaGetSymbolAddress((void**)&wxl, g_wx_l);
    cudaGetSymbolAddress((void**)&wdh, g_wdt_h);
    cudaGetSymbolAddress((void**)&wdl, g_wdt_l);

    float *xfpart, *xppart;
    cudaGetSymbolAddress((void**)&xfpart, g_xf_part);
    cudaGetSymbolAddress((void**)&xppart, g_xp_part);

    cudaFuncSetAttribute(gemm_tc2_kernel<0>,
                         cudaFuncAttributeMaxDynamicSharedMemorySize,
                         NSTAGE * STAGE_BYTES);
    cudaFuncSetAttribute(gemm_tc2_kernel<2>,
                         cudaFuncAttributeMaxDynamicSharedMemorySize,
                         NSTAGE * STAGE_BYTES);

    size_t ncvt = NWI + NWO + NWX + NWDT;
    cvt_weights_kernel<<<(unsigned)((ncvt + 255) / 256), 256>>>(
        in_proj, out_proj, x_proj, dt_w);
    ln_first_kernel<<<TT, 256>>>(x, bres, xnh, xnl, ln_w, ln_b);

    for (int l = 0; l < NLAY; l++) {
        // xz = xn @ Wi^T   (2048 x 3072, K=768)
        gemm_tc2_kernel<0><<<dim3((2 * DIN) / 128, TT / 128, 1), 256,
                             NSTAGE * STAGE_BYTES>>>(
            xnh, xnl,
            wih + (size_t)l * 2 * DIN * DD, wil + (size_t)l * 2 * DIN * DD,
            nullptr, bxz, 2 * DIN, DD, DD, 0);
        // xc = silu(conv(xi) + cb)
        conv_kernel<<<((TT / 4) * (DIN / 4)) / 256, 256>>>(
            bxz, bxc, xch, xcl,
            conv_w + (size_t)l * DIN * KCC, conv_b + (size_t)l * DIN);
        // dbc partials = xc @ Wx^T  (TC, N padded 128, split-K x8)
        gemm_tc2_kernel<0><<<dim3(1, TT / 128, XK), 256,
                             NSTAGE * STAGE_BYTES>>>(
            xch, xcl,
            wxh + (size_t)l * NRP * DIN, wxl + (size_t)l * NRP * DIN,
            nullptr, xppart, NRP, XKS, DIN, (size_t)TT * NRP);
        // reduce -> dtA bf16 hi/lo + compact dbcBC
        xred_kernel<<<(TT * 96 + 255) / 256, 256>>>();
        // dtT[d][t] = softplus(Wdt @ dtA^T + bdt)
        gemm_tc2_kernel<2><<<dim3(TT / 128, DIN / 128, 1), 256,
                             NSTAGE * STAGE_BYTES>>>(
            wdh + (size_t)l * DIN * DTK, wdl + (size_t)l * DIN * DTK,
            dtah, dtal,
            dt_b + (size_t)l * DIN, bdt, TT, DTK, DTK, 0);
        // chunked selective scan (p2 does the chain inline)
        scan_p1_kernel<<<dim3(BB * (DIN / 16), CH), 256>>>(
            bdt, bxc, A_log + (size_t)l * DIN * NSS);
        scan_p2_kernel<<<dim3(BB * (DIN / 16), CH), 256>>>(
            bdt, bxc, bxz, yh, yl,
            A_log + (size_t)l * DIN * NSS, D_skip + (size_t)l * DIN);
        // x_next partials = y @ Wo^T  split-K x3
        gemm_tc2_kernel<0><<<dim3(DD / 128, TT / 128, OK), 256,
                             NSTAGE * STAGE_BYTES>>>(
            yh, yl,
            woh + (size_t)l * DD * DIN, wol + (size_t)l * DD * DIN,
            nullptr, xfpart, DD, OKS, DIN, (size_t)TT * DD);
        // fused reduce + LN (next layer) or final LN
        if (l + 1 < NLAY) {
            ln_fuse_kernel<<<TT, 256>>>(bres, xnh, xnl,
                                        ln_w + (size_t)(l + 1) * DD,
                                        ln_b + (size_t)(l + 1) * DD);
        } else {
            final_fuse_kernel<<<TT, 256>>>(bres, fn_w, fn_b, out);
        }
    }
}